// round 7
// baseline (speedup 1.0000x reference)
#include <cuda_runtime.h>

#define Tn 128
#define Bn 8
#define En 256
#define Hn 512
#define G4 2048
#define NB2 128
#define NT2 256
#define WSTR 516   // 512 + pad -> 16B-aligned rows
typedef unsigned long long ull;

// ---------------- device scratch ----------------
__device__ float g_xs[Tn * Bn * G4];   // emb@Wih_s + b_s, [(t*8+b)*2048 + col]
__device__ float g_xt[Tn * Bn * G4];   // emb@Wih_t + b_t
// tagged h slots: [parity][block][64 floats]: 32 data + tag(u32) at [32]; zero-init
__device__ float g_slot[2][NB2][64];
__device__ unsigned int g_cnt;         // cold-path barrier counter

// ---------------- helpers ----------------
__device__ __forceinline__ ull fma2(ull a, ull b, ull c) {
    ull d;
    asm("fma.rn.f32x2 %0, %1, %2, %3;" : "=l"(d) : "l"(a), "l"(b), "l"(c));
    return d;
}
__device__ __forceinline__ float2 up2(ull a) {
    float2 f;
    asm("mov.b64 {%0, %1}, %2;" : "=f"(f.x), "=f"(f.y) : "l"(a));
    return f;
}
__device__ __forceinline__ float sigm(float x) {
    return __frcp_rn(1.f + __expf(-x));
}
__device__ __forceinline__ float tanh_f(float x) {
    return 1.f - 2.f * __frcp_rn(__expf(2.f * x) + 1.f);
}
__device__ __forceinline__ float4 ld_rel4(const float* p) {
    float4 v;
    asm volatile("ld.relaxed.gpu.global.v4.f32 {%0,%1,%2,%3}, [%4];"
                 : "=f"(v.x), "=f"(v.y), "=f"(v.z), "=f"(v.w) : "l"(p) : "memory");
    return v;
}
__device__ __forceinline__ void st_rel4(float* p, float4 v) {
    asm volatile("st.relaxed.gpu.global.v4.f32 [%0], {%1,%2,%3,%4};"
                 :: "l"(p), "f"(v.x), "f"(v.y), "f"(v.z), "f"(v.w) : "memory");
}
__device__ __forceinline__ unsigned ld_acq_u32(const unsigned* p) {
    unsigned v;
    asm volatile("ld.acquire.gpu.global.u32 %0, [%1];" : "=r"(v) : "l"(p) : "memory");
    return v;
}
__device__ __forceinline__ void st_release_u32(unsigned* p, unsigned v) {
    asm volatile("st.release.gpu.global.u32 [%0], %1;" :: "l"(p), "r"(v) : "memory");
}
// cold-path barrier
__device__ __forceinline__ void cold_arrive() {
    asm volatile("red.release.gpu.global.add.u32 [%0], 1;" :: "l"(&g_cnt) : "memory");
}
__device__ __forceinline__ void cold_poll(unsigned target) {
    unsigned v;
    do {
        asm volatile("ld.relaxed.gpu.global.u32 %0, [%1];"
                     : "=r"(v) : "l"(&g_cnt) : "memory");
    } while (v < target);
    asm volatile("fence.acq_rel.gpu;" ::: "memory");
}

// ---------------- kernel 1: gathered input GEMM (both matrices via z) ----------------
__global__ void __launch_bounds__(256) input_gemm(const int* __restrict__ tokens,
                                                  const float* __restrict__ etab,
                                                  const float* __restrict__ W0,
                                                  const float* __restrict__ bias0,
                                                  const float* __restrict__ W1,
                                                  const float* __restrict__ bias1) {
    __shared__ float As[16][128];
    __shared__ float Bs[16][128];
    const int which = blockIdx.z;
    const float* W    = which ? W1 : W0;
    const float* bias = which ? bias1 : bias0;
    float* outp = which ? g_xt : g_xs;

    if (blockIdx.x == 0 && blockIdx.y == 0 && blockIdx.z == 0 && threadIdx.x == 0)
        g_cnt = 0u;
    // reset slot tags (graph replays need fresh zero state)
    if (blockIdx.x < 2 && blockIdx.y == 0 && blockIdx.z == 0 && threadIdx.x < 128) {
        g_slot[blockIdx.x][threadIdx.x][32] = 0.f;   // tag = 0
        if (blockIdx.x == 0)                          // h(0) = 0 data
            for (int i = 0; i < 32; i++) g_slot[0][threadIdx.x][i] = 0.f;
    }

    const int m0 = blockIdx.y * 128;
    const int n0 = blockIdx.x * 128;
    const int tid = threadIdx.x;
    const int tr = tid >> 4, tc = tid & 15;

    float acc[8][8];
#pragma unroll
    for (int i = 0; i < 8; i++)
#pragma unroll
        for (int j = 0; j < 8; j++) acc[i][j] = 0.f;

    const int mA0 = tid >> 2;
    const int mA1 = (tid + 256) >> 2;
    const int kq0 = tid & 3;
    const int gm0 = m0 + mA0, gm1 = m0 + mA1;
    const long tok0 = tokens[(gm0 & 7) * Tn + (gm0 >> 3)];
    const long tok1 = tokens[(gm1 & 7) * Tn + (gm1 >> 3)];

    const int kb = tid >> 5;
    const int nq = tid & 31;

    for (int k0 = 0; k0 < En; k0 += 16) {
        float4 a0 = *(const float4*)&etab[tok0 * En + k0 + kq0 * 4];
        float4 a1 = *(const float4*)&etab[tok1 * En + k0 + kq0 * 4];
        As[kq0 * 4 + 0][mA0] = a0.x; As[kq0 * 4 + 1][mA0] = a0.y;
        As[kq0 * 4 + 2][mA0] = a0.z; As[kq0 * 4 + 3][mA0] = a0.w;
        As[kq0 * 4 + 0][mA1] = a1.x; As[kq0 * 4 + 1][mA1] = a1.y;
        As[kq0 * 4 + 2][mA1] = a1.z; As[kq0 * 4 + 3][mA1] = a1.w;

        *(float4*)&Bs[kb][nq * 4]     = *(const float4*)&W[(k0 + kb) * G4 + n0 + nq * 4];
        *(float4*)&Bs[kb + 8][nq * 4] = *(const float4*)&W[(k0 + kb + 8) * G4 + n0 + nq * 4];
        __syncthreads();

#pragma unroll
        for (int k = 0; k < 16; k++) {
            float av[8], bv[8];
            *(float4*)&av[0] = *(const float4*)&As[k][tr * 4];
            *(float4*)&av[4] = *(const float4*)&As[k][64 + tr * 4];
            *(float4*)&bv[0] = *(const float4*)&Bs[k][tc * 4];
            *(float4*)&bv[4] = *(const float4*)&Bs[k][64 + tc * 4];
#pragma unroll
            for (int i = 0; i < 8; i++)
#pragma unroll
                for (int j = 0; j < 8; j++) acc[i][j] += av[i] * bv[j];
        }
        __syncthreads();
    }

#pragma unroll
    for (int i = 0; i < 8; i++) {
        int m = m0 + ((i < 4) ? (tr * 4 + i) : (64 + tr * 4 + i - 4));
#pragma unroll
        for (int jh = 0; jh < 2; jh++) {
            int n = n0 + tc * 4 + jh * 64;
            float4 v;
            v.x = acc[i][jh * 4 + 0] + __ldg(&bias[n + 0]);
            v.y = acc[i][jh * 4 + 1] + __ldg(&bias[n + 1]);
            v.z = acc[i][jh * 4 + 2] + __ldg(&bias[n + 2]);
            v.w = acc[i][jh * 4 + 3] + __ldg(&bias[n + 3]);
            *(float4*)&outp[(long)m * G4 + n] = v;
        }
    }
}

// ---------------- kernel 2: persistent dual-LSTM, tagged-slot exchange ----------------
__global__ void __launch_bounds__(NT2) lstm_kernel(const float* __restrict__ Whh_s,
                                                   const float* __restrict__ Whh_t,
                                                   const float* __restrict__ Wmh_t,
                                                   float* __restrict__ out) {
    extern __shared__ float sm[];
    float* wstage = sm;                  // [16][WSTR] weight staging (transient)
    float* hs     = wstage + 16 * WSTR;  // [8][WSTR]  current h
    float* red    = hs + 8 * WSTR;       // [16][128]  k-group partials
    float* prebuf = red + 16 * 128;      // [128]      pre-activations (c2*8+b2)
    float* hsnew  = prebuf + 128;        // [32]       new h staging

    const int tid = threadIdx.x;
    const int bl  = blockIdx.x;
    const int kg  = tid >> 4, c  = tid & 15;   // stage-1 identity
    const int c2  = tid >> 3, b2 = tid & 7;    // stage-2 identity (tid<128)
    const int col2 = (c2 >> 2) * Hn + bl * 4 + (c2 & 3);
    const int krot = (kg & 1) << 2;            // bank-phase rotation per kg-parity
    const int slt  = tid >> 1, shalf = tid & 1; // consumer: 2 threads per slot

    ull wreg[16];
    float creg = 0.f;                    // c-state (act warp, tid<32)

    auto stageW = [&](const float* W) {
        __syncthreads();
        for (int i = tid; i < 16 * Hn; i += NT2) {
            int cc = i & 15, k = i >> 4;
            int cl = (cc >> 2) * Hn + bl * 4 + (cc & 3);
            wstage[cc * WSTR + k] = W[(long)k * G4 + cl];
        }
        __syncthreads();
#pragma unroll
        for (int i = 0; i < 16; i++)
            wreg[i] = *(const ull*)(wstage + c * WSTR + kg * 32 + 2 * i);
    };

    unsigned ncold = 0;
    auto gbar = [&]() {
        __syncthreads();
        ncold++;
        if (tid == 0) { cold_arrive(); cold_poll((unsigned)NB2 * ncold); }
        __syncthreads();
    };

    // poll+gather: 2 threads per slot; acquire tag then relaxed data loads
    auto load_slots = [&](int buf, unsigned want) {
        const float* slot = &g_slot[buf][slt][0];
        unsigned v;
        do { v = ld_acq_u32((const unsigned*)(slot + 32)); } while (v != want);
#pragma unroll
        for (int bi = 0; bi < 4; bi++) {
            int b = shalf * 4 + bi;
            float4 d = ld_rel4(slot + b * 4);
            *(float4*)&hs[b * WSTR + slt * 4] = d;
        }
    };

    auto stage1 = [&]() {
        float part[8];
#pragma unroll
        for (int b = 0; b < 8; b++) {
            const float* hb = hs + b * WSTR + kg * 32;
            ull a0 = 0ull, a1 = 0ull;
#pragma unroll
            for (int kq = 0; kq < 8; kq++) {
                int kk = (kq + krot) & 7;
                ulonglong2 hv = *(const ulonglong2*)(hb + kk * 4);
                a0 = fma2(hv.x, wreg[2 * kk], a0);
                a1 = fma2(hv.y, wreg[2 * kk + 1], a1);
            }
            float2 f0 = up2(a0), f1 = up2(a1);
            part[b] = (f0.x + f1.x) + (f0.y + f1.y);
        }
        *(float4*)&red[kg * 128 + c * 8]     = make_float4(part[0], part[1], part[2], part[3]);
        *(float4*)&red[kg * 128 + c * 8 + 4] = make_float4(part[4], part[5], part[6], part[7]);
    };
    auto stage2 = [&](float xv) {   // tid<128 only
        float p = xv;
#pragma unroll
        for (int g = 0; g < 16; g++) p += red[g * 128 + tid];
        return p;
    };

    float xv = 0.f;  // prefetched x(t)

    // one step: consume (rbuf, want) -> produce (wbuf, tago)
    auto do_step = [&](const float* xnextbase, float rcv, int t,
                       int rbuf, unsigned want, int wbuf, unsigned tago, float* outp) {
        load_slots(rbuf, want);
        __syncthreads();
        stage1();
        __syncthreads();
        if (tid < 128) prebuf[tid] = stage2(xv + rcv);
        __syncthreads();
        if (tid < 32) {
            int bb = tid >> 2, j = tid & 3;
            float iv = prebuf[(0  + j) * 8 + bb];
            float fv = prebuf[(4  + j) * 8 + bb];
            float gv = prebuf[(8  + j) * 8 + bb];
            float ov = prebuf[(12 + j) * 8 + bb];
            float cn = sigm(fv) * creg + sigm(iv) * tanh_f(gv);
            float hn = sigm(ov) * tanh_f(cn);
            creg = cn;
            hsnew[bb * 4 + j] = hn;
            __syncwarp();
            if (tid < 8 && outp) {
                float4 v = *(const float4*)&hsnew[tid * 4];
                __stcg((float4*)&outp[(long)(tid * Tn + t) * Hn + bl * 4], v);
            }
            if (tid == 0) {
                float* slot = &g_slot[wbuf][bl][0];
#pragma unroll
                for (int i = 0; i < 8; i++)
                    st_rel4(slot + i * 4, *(const float4*)&hsnew[i * 4]);
                st_release_u32((unsigned*)(slot + 32), tago);  // release covers data
            }
        }
        if (tid < 128 && xnextbase)
            xv = __ldcg(&xnextbase[(long)(((t + 1) & (Tn - 1)) * Bn + b2) * G4 + col2]);
        // no trailing barrier: next step's per-slot acquire-poll IS the sync
    };

    // ---- init ----
    stageW(Whh_s);
    gbar();   // ensures GEMM-kernel tag/zero resets + weights staged are globally done

    // ---- shared LSTM: steps g=0..127; slot[0] pre-tagged 0 with h=0 ----
    if (tid < 128) xv = __ldcg(&g_xs[(long)(0 * Bn + b2) * G4 + col2]);
    for (int t = 0; t < Tn; t++)
        do_step(g_xs, 0.f, t, t & 1, (unsigned)t, (t + 1) & 1, (unsigned)(t + 1), nullptr);

    // snapshot h_last: produced by step 127 into buf 0 with tag 128
    load_slots(0, 128u);
    __syncthreads();
    gbar();   // all blocks hold h_last before anyone overwrites buf 0

    // rc = h_last @ Wmh_t (constant across task steps)
    stageW(Wmh_t);
    stage1();
    __syncthreads();
    float rcv = (tid < 128) ? stage2(0.f) : 0.f;
    stageW(Whh_t);    // leading syncthreads protects red/hs reads above
    if (tid < 32) creg = 0.f;
    // publish task-phase zero state: buf 0, tag 130
    if (tid == 0) {
        float* slot = &g_slot[0][bl][0];
#pragma unroll
        for (int i = 0; i < 8; i++)
            st_rel4(slot + i * 4, make_float4(0.f, 0.f, 0.f, 0.f));
        st_release_u32((unsigned*)(slot + 32), 130u);
    }

    // ---- task LSTM: steps g=130+i ----
    if (tid < 128) xv = __ldcg(&g_xt[(long)(0 * Bn + b2) * G4 + col2]);
    for (int t = 0; t < Tn; t++)
        do_step(g_xt, rcv, t, t & 1, (unsigned)(130 + t), (t + 1) & 1,
                (unsigned)(131 + t), out);
}

// ---------------- launch ----------------
extern "C" void kernel_launch(void* const* d_in, const int* in_sizes, int n_in,
                              void* d_out, int out_size) {
    const int sh = (n_in == 14) ? 0 : 1;
    const int*   tokens = (const int*)d_in[0];
    const float* etab   = (const float*)d_in[2 - sh];
    const float* Wih_s  = (const float*)d_in[3 - sh];
    const float* Whh_s  = (const float*)d_in[4 - sh];
    const float* b_s    = (const float*)d_in[5 - sh];
    const float* Wih_t  = (const float*)d_in[10 - sh];
    const float* Whh_t  = (const float*)d_in[11 - sh];
    const float* Wmh_t  = (const float*)d_in[12 - sh];
    const float* b_t    = (const float*)d_in[13 - sh];
    float* out = (float*)d_out;

    const int smem2 = (16 * WSTR + 8 * WSTR + 16 * 128 + 128 + 32) * (int)sizeof(float);
    cudaFuncSetAttribute(lstm_kernel, cudaFuncAttributeMaxDynamicSharedMemorySize, smem2);

    dim3 gg(G4 / 128, (Tn * Bn) / 128, 2);  // (16, 8, 2)
    input_gemm<<<gg, 256>>>(tokens, etab, Wih_s, b_s, Wih_t, b_t);
    lstm_kernel<<<NB2, NT2, smem2>>>(Whh_s, Whh_t, Wmh_t, out);
}